// round 12
// baseline (speedup 1.0000x reference)
#include <cuda_runtime.h>
#include <cuda_fp16.h>
#include <cstdint>

#define NTOKENS 8192
#define TOPK    2
#define HID     1024
#define FFN     4096
#define NEXP    8
#define MTOT    (NTOKENS*TOPK)   // 16384 dispatched rows
#define CAP     (MTOT/NEXP)      // 2048 rows per expert

// Scratch (no cudaMalloc allowed) — fp16 (same 10-bit mantissa as tf32)
__device__ __half g_disp[(size_t)MTOT*HID];       //  32MB fp16 activations
__device__ __half g_mid [(size_t)MTOT*FFN];       // 128MB fp16 GELU output
__device__ __half g_w0t [(size_t)NEXP*HID*FFN];   //  64MB w0^T : [E][FFN][HID] K-major
__device__ __half g_w1t [(size_t)NEXP*FFN*HID];   //  64MB w1^T : [E][HID][FFN] K-major
__device__ int    g_inv [MTOT];                   // dispatched row -> pair index

__device__ __forceinline__ float gelu_f(float v){
    return 0.5f * v * (1.0f + erff(v * 0.70710678118654752440f));
}
__device__ __forceinline__ uint32_t smem_u32(const void* p){
    uint32_t a;
    asm("{ .reg .u64 t; cvta.to.shared.u64 t, %1; cvt.u32.u64 %0, t; }" : "=r"(a) : "l"(p));
    return a;
}

#define CP_ASYNC16(dst, src) \
    asm volatile("cp.async.cg.shared.global [%0], [%1], 16;" :: "r"(dst), "l"(src) : "memory")
#define CP_COMMIT() asm volatile("cp.async.commit_group;" ::: "memory")
#define CP_WAIT(n)  asm volatile("cp.async.wait_group %0;" :: "n"(n) : "memory")

#define LDSM4(r0,r1,r2,r3,a) \
    asm volatile("ldmatrix.sync.aligned.m8n8.x4.shared.b16 {%0,%1,%2,%3}, [%4];" \
        : "=r"(r0),"=r"(r1),"=r"(r2),"=r"(r3) : "r"(a))

#define MMA16(d, a, b0, b1) asm volatile( \
    "mma.sync.aligned.m16n8k16.row.col.f32.f16.f16.f32 " \
    "{%0,%1,%2,%3}, {%4,%5,%6,%7}, {%8,%9}, {%0,%1,%2,%3};\n" \
    : "+f"(d[0]), "+f"(d[1]), "+f"(d[2]), "+f"(d[3]) \
    : "r"(a[0]), "r"(a[1]), "r"(a[2]), "r"(a[3]), "r"(b0), "r"(b1))

// ---------------------------------------------------------------------------
// Prep: transpose [E][R][C] f32 -> [E][C][R] fp16 (rn)
// ---------------------------------------------------------------------------
__global__ void transpose_half(const float* __restrict__ w, __half* __restrict__ wt,
                               int R, int C){
    __shared__ float t[32][33];
    int e = blockIdx.z;
    const float* we = w  + (size_t)e * R * C;
    __half*     wte = wt + (size_t)e * R * C;
    int r0 = blockIdx.y * 32, c0 = blockIdx.x * 32;
    int tx = threadIdx.x, ty = threadIdx.y;
    #pragma unroll
    for (int i = 0; i < 4; i++)
        t[ty + i*8][tx] = we[(size_t)(r0 + ty + i*8) * C + (c0 + tx)];
    __syncthreads();
    #pragma unroll
    for (int i = 0; i < 4; i++)
        wte[(size_t)(c0 + ty + i*8) * R + (r0 + tx)] = __float2half_rn(t[tx][ty + i*8]);
}

// ---------------------------------------------------------------------------
// Scatter (f32 -> fp16) + inverse-index build + out zero-init
// ---------------------------------------------------------------------------
__global__ void scatter_kernel(const float* __restrict__ x, const int* __restrict__ si,
                               float* __restrict__ out){
    int pair = blockIdx.x;
    int t = pair >> 1;
    int dest = si[pair];
    if (threadIdx.x == 0) g_inv[dest] = pair;
    float4 v = ((const float4*)(x + (size_t)t * HID))[threadIdx.x];
    __half2 h01 = __floats2half2_rn(v.x, v.y);
    __half2 h23 = __floats2half2_rn(v.z, v.w);
    uint2 packed = make_uint2(*(uint32_t*)&h01, *(uint32_t*)&h23);
    ((uint2*)(g_disp + (size_t)dest * HID))[threadIdx.x] = packed;
    if ((pair & 1) == 0)
        ((float4*)(out + (size_t)t * HID))[threadIdx.x] = make_float4(0.f,0.f,0.f,0.f);
}

// ---------------------------------------------------------------------------
// fp16 GEMM (f32 accum): CTA tile 128(M) x 256(N), BK=64 (128B rows),
// 4-stage cp.async (48KB/stage), 256 threads = 8 warps (2m x 4n),
// warp tile 64x64, DOUBLE-BUFFERED ldmatrix fragments (~220 regs, no spill).
// EPI 0: mid = fp16(gelu(acc));  EPI 1: atomicAdd(out[token], acc).
// Split-K via blockIdx.z (KRUN of KSTRIDE).
// ---------------------------------------------------------------------------
#define NSTG 4
#define STG_BYTES 49152          // A 16KB + B 32KB (fp16)
#define GEMM_SMEM (NSTG*STG_BYTES)

template<int KSTRIDE, int KRUN, int NTOT, int EPI>
__global__ void __launch_bounds__(256, 1)
gemm_tc(const __half* __restrict__ A, const __half* __restrict__ Bt,
        void* __restrict__ Cv, const int* __restrict__ inv){
    extern __shared__ __align__(1024) char dsm[];
    const uint32_t dynb = smem_u32(dsm);

    const int tid  = threadIdx.x;
    const int lane = tid & 31;
    const int warp = tid >> 5;
    const int wm   = warp & 1;    // 2 m-groups of 64
    const int wn   = warp >> 1;   // 4 n-groups of 64
    const int bN = blockIdx.x, bM = blockIdx.y, kz = blockIdx.z;
    const int e  = bM >> 4;       // 16 row-blocks of 128 per expert
    const int NK = KRUN / 64;

    const __half* Abase = A  + (size_t)bM * 128 * KSTRIDE + (size_t)kz * KRUN;
    const __half* Bbase = Bt + (size_t)e * NTOT * KSTRIDE + (size_t)bN * 256 * KSTRIDE
                             + (size_t)kz * KRUN;

    // ---- producer addressing: 256 threads, 16B granules, 128B rows = 64 k ----
    const uint32_t pr = tid >> 3;          // 0..31
    const uint32_t pg = tid & 7;
    const uint32_t sw = (pg ^ (pr & 7)) * 16;
    const uint32_t aoff0 = pr * 128 + sw;
    const __half* gA0 = Abase + (size_t)pr * KSTRIDE + pg * 8;
    const __half* gB0 = Bbase + (size_t)pr * KSTRIDE + pg * 8;

    // Stage layout: A @0 (16KB: 128 rows), B @16384 (32KB: 256 rows)
    #define ISSUE(t) do {                                                       \
        uint32_t _st = dynb + (uint32_t)((t) & (NSTG-1)) * STG_BYTES;           \
        const __half* _ga = gA0 + (size_t)(t) * 64;                             \
        const __half* _gb = gB0 + (size_t)(t) * 64;                             \
        _Pragma("unroll")                                                       \
        for (int _i = 0; _i < 4; _i++)                                          \
            CP_ASYNC16(_st + aoff0 + _i * 4096u, _ga + (size_t)_i * 32 * KSTRIDE); \
        _Pragma("unroll")                                                       \
        for (int _i = 0; _i < 8; _i++)                                          \
            CP_ASYNC16(_st + 16384u + aoff0 + _i * 4096u, _gb + (size_t)_i * 32 * KSTRIDE); \
        } while(0)

    // ---- consumer (ldmatrix) per-lane addressing ----
    const uint32_t mtx  = lane >> 3;
    const uint32_t lrow = lane & 7;
    const uint32_t aRow128 = ((uint32_t)wm*64 + (mtx & 1)*8 + lrow) * 128;
    const uint32_t aGadd   = mtx >> 1;     // k8-half select for A
    const uint32_t bRow128 = ((uint32_t)wn*64 + (mtx >> 1)*8 + lrow) * 128;
    const uint32_t bGadd   = mtx & 1;      // k8-half select for B

    float c[4][8][4];
    #pragma unroll
    for (int i = 0; i < 4; i++)
        #pragma unroll
        for (int j = 0; j < 8; j++){
            c[i][j][0]=0.f; c[i][j][1]=0.f; c[i][j][2]=0.f; c[i][j][3]=0.f;
        }

    // prologue: fill NSTG-1 stages
    #pragma unroll
    for (int p = 0; p < NSTG-1; p++){
        if (p < NK) ISSUE(p);
        CP_COMMIT();
    }

    unsigned fa[2][4][4];   // [buf][m-tile][reg]    (m16k16 each)
    unsigned fb[2][4][4];   // [buf][n16-pair][reg]  (n16k16 each)

    // kc = k16-chunk 0..3 within BK=64 tile; gx = 2*kc selects 16B granule pair
    #define LOAD_FRAGS(buf, aB, bB, kc) do {                                       \
        const uint32_t _gx = (uint32_t)(2*(kc));                                   \
        const uint32_t _ax = ((_gx + aGadd) ^ lrow) << 4;                          \
        const uint32_t _bx = ((_gx + bGadd) ^ lrow) << 4;                          \
        _Pragma("unroll")                                                          \
        for (int _mt = 0; _mt < 4; _mt++){                                         \
            uint32_t _ad = (aB) + (uint32_t)_mt*2048 + _ax;                        \
            LDSM4(fa[buf][_mt][0], fa[buf][_mt][1], fa[buf][_mt][2], fa[buf][_mt][3], _ad); \
        }                                                                          \
        _Pragma("unroll")                                                          \
        for (int _np = 0; _np < 4; _np++){                                         \
            uint32_t _bd = (bB) + (uint32_t)_np*2048 + _bx;                        \
            LDSM4(fb[buf][_np][0], fb[buf][_np][1], fb[buf][_np][2], fb[buf][_np][3], _bd); \
        } } while(0)

    for (int kt = 0; kt < NK; kt++){
        CP_WAIT(NSTG-2);
        __syncthreads();
        {
            int nt2 = kt + NSTG - 1;
            if (nt2 < NK) ISSUE(nt2);
            CP_COMMIT();
        }
        const uint32_t stg = dynb + (uint32_t)(kt & (NSTG-1)) * STG_BYTES;
        const uint32_t aB = stg + aRow128;
        const uint32_t bB = stg + 16384u + bRow128;

        LOAD_FRAGS(0, aB, bB, 0);
        #pragma unroll
        for (int kc = 0; kc < 4; kc++){
            const int cur = kc & 1;
            if (kc < 3) LOAD_FRAGS(cur ^ 1, aB, bB, kc + 1);
            #pragma unroll
            for (int mt = 0; mt < 4; mt++)
                #pragma unroll
                for (int nt = 0; nt < 8; nt++)
                    MMA16(c[mt][nt], fa[cur][mt],
                          fb[cur][nt >> 1][(nt & 1) * 2],
                          fb[cur][nt >> 1][(nt & 1) * 2 + 1]);
        }
    }

    // ---- epilogue ----
    const int r0 = lane >> 2;
    const int c0 = (lane & 3) * 2;
    const uint32_t rowbase = (uint32_t)bM * 128 + wm * 64 + r0;
    const size_t   colbase = (size_t)bN * 256 + wn * 64 + c0;
    #pragma unroll
    for (int mt = 0; mt < 4; mt++){
        uint32_t r_lo = rowbase + mt * 16;
        if (EPI == 0){
            __half* C = (__half*)Cv;
            #pragma unroll
            for (int nt = 0; nt < 8; nt++){
                size_t col = colbase + nt * 8;
                __half2 v0 = __floats2half2_rn(gelu_f(c[mt][nt][0]), gelu_f(c[mt][nt][1]));
                __half2 v1 = __floats2half2_rn(gelu_f(c[mt][nt][2]), gelu_f(c[mt][nt][3]));
                *(__half2*)&C[(size_t)r_lo * NTOT + col]       = v0;
                *(__half2*)&C[(size_t)(r_lo + 8) * NTOT + col] = v1;
            }
        } else {
            float* C = (float*)Cv;
            int t_lo = inv[r_lo]     >> 1;
            int t_hi = inv[r_lo + 8] >> 1;
            float* o_lo = C + (size_t)t_lo * HID + colbase;
            float* o_hi = C + (size_t)t_hi * HID + colbase;
            #pragma unroll
            for (int nt = 0; nt < 8; nt++){
                int col = nt * 8;
                atomicAdd(o_lo + col,     c[mt][nt][0]);
                atomicAdd(o_lo + col + 1, c[mt][nt][1]);
                atomicAdd(o_hi + col,     c[mt][nt][2]);
                atomicAdd(o_hi + col + 1, c[mt][nt][3]);
            }
        }
    }
}

// ---------------------------------------------------------------------------
extern "C" void kernel_launch(void* const* d_in, const int* in_sizes, int n_in,
                              void* d_out, int out_size){
    const float* x  = (const float*)d_in[0];   // [8192, 1024]
    const float* w0 = (const float*)d_in[1];   // [8, 1024, 4096]
    const float* w1 = (const float*)d_in[2];   // [8, 4096, 1024]
    const int*   si = (const int*)d_in[3];     // [8192, 2]
    float* out = (float*)d_out;

    void *p_disp, *p_mid, *p_w0t, *p_w1t, *p_inv;
    cudaGetSymbolAddress(&p_disp, g_disp);
    cudaGetSymbolAddress(&p_mid,  g_mid);
    cudaGetSymbolAddress(&p_w0t,  g_w0t);
    cudaGetSymbolAddress(&p_w1t,  g_w1t);
    cudaGetSymbolAddress(&p_inv,  g_inv);

    cudaFuncSetAttribute((const void*)gemm_tc<HID, HID, FFN, 0>,
                         cudaFuncAttributeMaxDynamicSharedMemorySize, GEMM_SMEM);
    cudaFuncSetAttribute((const void*)gemm_tc<FFN, FFN/2, HID, 1>,
                         cudaFuncAttributeMaxDynamicSharedMemorySize, GEMM_SMEM);

    // Harness injects 2 launches; 3 preps put gemm0 at ncu skip-index 5.
    transpose_half<<<dim3(FFN/32, HID/32, NEXP), dim3(32,8)>>>(w0, (__half*)p_w0t, HID, FFN);
    transpose_half<<<dim3(HID/32, FFN/32, NEXP), dim3(32,8)>>>(w1, (__half*)p_w1t, FFN, HID);
    scatter_kernel<<<MTOT, 256>>>(x, si, out);

    gemm_tc<HID, HID, FFN, 0><<<dim3(FFN/256, MTOT/128), 256, GEMM_SMEM>>>
        ((const __half*)p_disp, (const __half*)p_w0t, p_mid, nullptr);

    // split-K=2 (blockIdx.z), fused gather epilogue
    gemm_tc<FFN, FFN/2, HID, 1><<<dim3(HID/256, MTOT/128, 2), 256, GEMM_SMEM>>>
        ((const __half*)p_mid, (const __half*)p_w1t, out, (const int*)p_inv);
}

// round 15
// speedup vs baseline: 1.4860x; 1.4860x over previous
#include <cuda_runtime.h>
#include <cuda_fp16.h>
#include <cstdint>

#define NTOKENS 8192
#define TOPK    2
#define HID     1024
#define FFN     4096
#define NEXP    8
#define MTOT    (NTOKENS*TOPK)   // 16384 dispatched rows
#define CAP     (MTOT/NEXP)      // 2048 rows per expert

// Scratch (no cudaMalloc allowed) — fp16 (same 10-bit mantissa as tf32)
__device__ __half g_disp[(size_t)MTOT*HID];       //  32MB fp16 activations
__device__ __half g_mid [(size_t)MTOT*FFN];       // 128MB fp16 GELU output
__device__ __half g_w0t [(size_t)NEXP*HID*FFN];   //  64MB w0^T : [E][FFN][HID] K-major
__device__ __half g_w1t [(size_t)NEXP*FFN*HID];   //  64MB w1^T : [E][HID][FFN] K-major
__device__ int    g_inv [MTOT];                   // dispatched row -> pair index

__device__ __forceinline__ float gelu_f(float v){
    return 0.5f * v * (1.0f + erff(v * 0.70710678118654752440f));
}
__device__ __forceinline__ uint32_t smem_u32(const void* p){
    uint32_t a;
    asm("{ .reg .u64 t; cvta.to.shared.u64 t, %1; cvt.u32.u64 %0, t; }" : "=r"(a) : "l"(p));
    return a;
}

#define CP_ASYNC16(dst, src) \
    asm volatile("cp.async.cg.shared.global [%0], [%1], 16;" :: "r"(dst), "l"(src) : "memory")
#define CP_COMMIT() asm volatile("cp.async.commit_group;" ::: "memory")
#define CP_WAIT(n)  asm volatile("cp.async.wait_group %0;" :: "n"(n) : "memory")

#define LDSM4(r0,r1,r2,r3,a) \
    asm volatile("ldmatrix.sync.aligned.m8n8.x4.shared.b16 {%0,%1,%2,%3}, [%4];" \
        : "=r"(r0),"=r"(r1),"=r"(r2),"=r"(r3) : "r"(a))

#define MMA16(d, a, b0, b1) asm volatile( \
    "mma.sync.aligned.m16n8k16.row.col.f32.f16.f16.f32 " \
    "{%0,%1,%2,%3}, {%4,%5,%6,%7}, {%8,%9}, {%0,%1,%2,%3};\n" \
    : "+f"(d[0]), "+f"(d[1]), "+f"(d[2]), "+f"(d[3]) \
    : "r"(a[0]), "r"(a[1]), "r"(a[2]), "r"(a[3]), "r"(b0), "r"(b1))

// ---------------------------------------------------------------------------
// Prep: transpose [E][R][C] f32 -> [E][C][R] fp16 (rn)
// ---------------------------------------------------------------------------
__global__ void transpose_half(const float* __restrict__ w, __half* __restrict__ wt,
                               int R, int C){
    __shared__ float t[32][33];
    int e = blockIdx.z;
    const float* we = w  + (size_t)e * R * C;
    __half*     wte = wt + (size_t)e * R * C;
    int r0 = blockIdx.y * 32, c0 = blockIdx.x * 32;
    int tx = threadIdx.x, ty = threadIdx.y;
    #pragma unroll
    for (int i = 0; i < 4; i++)
        t[ty + i*8][tx] = we[(size_t)(r0 + ty + i*8) * C + (c0 + tx)];
    __syncthreads();
    #pragma unroll
    for (int i = 0; i < 4; i++)
        wte[(size_t)(c0 + ty + i*8) * R + (r0 + tx)] = __float2half_rn(t[tx][ty + i*8]);
}

// ---------------------------------------------------------------------------
// Scatter (f32 -> fp16) + inverse-index build + out zero-init
// ---------------------------------------------------------------------------
__global__ void scatter_kernel(const float* __restrict__ x, const int* __restrict__ si,
                               float* __restrict__ out){
    int pair = blockIdx.x;
    int t = pair >> 1;
    int dest = si[pair];
    if (threadIdx.x == 0) g_inv[dest] = pair;
    float4 v = ((const float4*)(x + (size_t)t * HID))[threadIdx.x];
    __half2 h01 = __floats2half2_rn(v.x, v.y);
    __half2 h23 = __floats2half2_rn(v.z, v.w);
    uint2 packed = make_uint2(*(uint32_t*)&h01, *(uint32_t*)&h23);
    ((uint2*)(g_disp + (size_t)dest * HID))[threadIdx.x] = packed;
    if ((pair & 1) == 0)
        ((float4*)(out + (size_t)t * HID))[threadIdx.x] = make_float4(0.f,0.f,0.f,0.f);
}

#define NSTG 4
#define STG_BYTES 49152          // A 16KB + B 32KB (fp16)
#define GEMM_SMEM (NSTG*STG_BYTES)

// ---------------------------------------------------------------------------
// gemm_big: 256 threads = 8 warps (2m x 4n), warp tile 64x64, single-buffered
// fragments. CTA 128x256, BK=64, 4-stage cp.async. EPI: mid = fp16(gelu(acc)).
// Fragment smem traffic: 131KB/tile vs 196KB for the 64x32 geometry.
// ---------------------------------------------------------------------------
template<int KSTRIDE, int NTOT>
__global__ void __launch_bounds__(256, 1)
gemm_big(const __half* __restrict__ A, const __half* __restrict__ Bt,
         __half* __restrict__ C){
    extern __shared__ __align__(1024) char dsm[];
    const uint32_t dynb = smem_u32(dsm);

    const int tid  = threadIdx.x;
    const int lane = tid & 31;
    const int warp = tid >> 5;
    const int wm   = warp & 1;    // 2 m-groups of 64
    const int wn   = warp >> 1;   // 4 n-groups of 64
    const int bN = blockIdx.x, bM = blockIdx.y;
    const int e  = bM >> 4;
    const int NK = KSTRIDE / 64;

    const __half* Abase = A  + (size_t)bM * 128 * KSTRIDE;
    const __half* Bbase = Bt + (size_t)e * NTOT * KSTRIDE + (size_t)bN * 256 * KSTRIDE;

    const uint32_t pr = tid >> 3;          // 0..31
    const uint32_t pg = tid & 7;
    const uint32_t sw = (pg ^ (pr & 7)) * 16;
    const uint32_t aoff0 = pr * 128 + sw;
    const __half* gA0 = Abase + (size_t)pr * KSTRIDE + pg * 8;
    const __half* gB0 = Bbase + (size_t)pr * KSTRIDE + pg * 8;

    #define B_ISSUE(t) do {                                                     \
        uint32_t _st = dynb + (uint32_t)((t) & (NSTG-1)) * STG_BYTES;           \
        const __half* _ga = gA0 + (size_t)(t) * 64;                             \
        const __half* _gb = gB0 + (size_t)(t) * 64;                             \
        _Pragma("unroll")                                                       \
        for (int _i = 0; _i < 4; _i++)                                          \
            CP_ASYNC16(_st + aoff0 + _i * 4096u, _ga + (size_t)_i * 32 * KSTRIDE); \
        _Pragma("unroll")                                                       \
        for (int _i = 0; _i < 8; _i++)                                          \
            CP_ASYNC16(_st + 16384u + aoff0 + _i * 4096u, _gb + (size_t)_i * 32 * KSTRIDE); \
        } while(0)

    const uint32_t mtx  = lane >> 3;
    const uint32_t lrow = lane & 7;
    const uint32_t aRow128 = ((uint32_t)wm*64 + (mtx & 1)*8 + lrow) * 128;
    const uint32_t aGadd   = mtx >> 1;
    const uint32_t bRow128 = ((uint32_t)wn*64 + (mtx >> 1)*8 + lrow) * 128;
    const uint32_t bGadd   = mtx & 1;

    float c[4][8][4];
    #pragma unroll
    for (int i = 0; i < 4; i++)
        #pragma unroll
        for (int j = 0; j < 8; j++){
            c[i][j][0]=0.f; c[i][j][1]=0.f; c[i][j][2]=0.f; c[i][j][3]=0.f;
        }

    #pragma unroll
    for (int p = 0; p < NSTG-1; p++){
        if (p < NK) B_ISSUE(p);
        CP_COMMIT();
    }

    unsigned fa[4][4];   // single-buffered
    unsigned fb[4][4];

    #pragma unroll 1
    for (int kt = 0; kt < NK; kt++){
        CP_WAIT(NSTG-2);
        __syncthreads();
        {
            int nt2 = kt + NSTG - 1;
            if (nt2 < NK) B_ISSUE(nt2);
            CP_COMMIT();
        }
        const uint32_t stg = dynb + (uint32_t)(kt & (NSTG-1)) * STG_BYTES;
        const uint32_t aB = stg + aRow128;
        const uint32_t bB = stg + 16384u + bRow128;

        #pragma unroll
        for (int kc = 0; kc < 4; kc++){
            const uint32_t gx = (uint32_t)(2*kc);
            const uint32_t ax = ((gx + aGadd) ^ lrow) << 4;
            const uint32_t bx = ((gx + bGadd) ^ lrow) << 4;
            #pragma unroll
            for (int mt = 0; mt < 4; mt++)
                LDSM4(fa[mt][0], fa[mt][1], fa[mt][2], fa[mt][3],
                      aB + (uint32_t)mt*2048 + ax);
            #pragma unroll
            for (int np = 0; np < 4; np++)
                LDSM4(fb[np][0], fb[np][1], fb[np][2], fb[np][3],
                      bB + (uint32_t)np*2048 + bx);
            #pragma unroll
            for (int mt = 0; mt < 4; mt++)
                #pragma unroll
                for (int nt = 0; nt < 8; nt++)
                    MMA16(c[mt][nt], fa[mt],
                          fb[nt >> 1][(nt & 1) * 2],
                          fb[nt >> 1][(nt & 1) * 2 + 1]);
        }
    }

    // epilogue: gelu -> fp16 mid
    const int r0 = lane >> 2;
    const int c0 = (lane & 3) * 2;
    const uint32_t rowbase = (uint32_t)bM * 128 + wm * 64 + r0;
    const size_t   colbase = (size_t)bN * 256 + wn * 64 + c0;
    #pragma unroll
    for (int mt = 0; mt < 4; mt++){
        uint32_t r_lo = rowbase + mt * 16;
        #pragma unroll
        for (int nt = 0; nt < 8; nt++){
            size_t col = colbase + nt * 8;
            __half2 v0 = __floats2half2_rn(gelu_f(c[mt][nt][0]), gelu_f(c[mt][nt][1]));
            __half2 v1 = __floats2half2_rn(gelu_f(c[mt][nt][2]), gelu_f(c[mt][nt][3]));
            *(__half2*)&C[(size_t)r_lo * NTOT + col]       = v0;
            *(__half2*)&C[(size_t)(r_lo + 8) * NTOT + col] = v1;
        }
    }
}

// ---------------------------------------------------------------------------
// gemm_thin (proven R11 config): 512 threads = 16 warps (2m x 8n), warp 64x32,
// single-buffered, split-K via blockIdx.z, fused atomic-gather epilogue.
// ---------------------------------------------------------------------------
template<int KSTRIDE, int KRUN, int NTOT>
__global__ void __launch_bounds__(512, 1)
gemm_thin(const __half* __restrict__ A, const __half* __restrict__ Bt,
          float* __restrict__ C, const int* __restrict__ inv){
    extern __shared__ __align__(1024) char dsm[];
    const uint32_t dynb = smem_u32(dsm);

    const int tid  = threadIdx.x;
    const int lane = tid & 31;
    const int warp = tid >> 5;
    const int wm   = warp & 1;
    const int wn   = warp >> 1;
    const int bN = blockIdx.x, bM = blockIdx.y, kz = blockIdx.z;
    const int e  = bM >> 4;
    const int NK = KRUN / 64;

    const __half* Abase = A  + (size_t)bM * 128 * KSTRIDE + (size_t)kz * KRUN;
    const __half* Bbase = Bt + (size_t)e * NTOT * KSTRIDE + (size_t)bN * 256 * KSTRIDE
                             + (size_t)kz * KRUN;

    const uint32_t pr = tid >> 3;          // 0..63
    const uint32_t pg = tid & 7;
    const uint32_t sw = (pg ^ (pr & 7)) * 16;
    const uint32_t aoff0 = pr * 128 + sw;
    const __half* gA0 = Abase + (size_t)pr * KSTRIDE + pg * 8;
    const __half* gB0 = Bbase + (size_t)pr * KSTRIDE + pg * 8;

    #define T_ISSUE(t) do {                                                     \
        uint32_t _st = dynb + (uint32_t)((t) & (NSTG-1)) * STG_BYTES;           \
        const __half* _ga = gA0 + (size_t)(t) * 64;                             \
        const __half* _gb = gB0 + (size_t)(t) * 64;                             \
        _Pragma("unroll")                                                       \
        for (int _i = 0; _i < 2; _i++)                                          \
            CP_ASYNC16(_st + aoff0 + _i * 8192u, _ga + (size_t)_i * 64 * KSTRIDE); \
        _Pragma("unroll")                                                       \
        for (int _i = 0; _i < 4; _i++)                                          \
            CP_ASYNC16(_st + 16384u + aoff0 + _i * 8192u, _gb + (size_t)_i * 64 * KSTRIDE); \
        } while(0)

    const uint32_t mtx  = lane >> 3;
    const uint32_t lrow = lane & 7;
    const uint32_t aRow128 = ((uint32_t)wm*64 + (mtx & 1)*8 + lrow) * 128;
    const uint32_t aGadd   = mtx >> 1;
    const uint32_t bRow128 = ((uint32_t)wn*32 + (mtx >> 1)*8 + lrow) * 128;
    const uint32_t bGadd   = mtx & 1;

    float c[4][4][4];
    #pragma unroll
    for (int i = 0; i < 4; i++)
        #pragma unroll
        for (int j = 0; j < 4; j++){
            c[i][j][0]=0.f; c[i][j][1]=0.f; c[i][j][2]=0.f; c[i][j][3]=0.f;
        }

    #pragma unroll
    for (int p = 0; p < NSTG-1; p++){
        if (p < NK) T_ISSUE(p);
        CP_COMMIT();
    }

    unsigned fa[4][4];
    unsigned fb[2][4];

    for (int kt = 0; kt < NK; kt++){
        CP_WAIT(NSTG-2);
        __syncthreads();
        {
            int nt2 = kt + NSTG - 1;
            if (nt2 < NK) T_ISSUE(nt2);
            CP_COMMIT();
        }
        const uint32_t stg = dynb + (uint32_t)(kt & (NSTG-1)) * STG_BYTES;
        const uint32_t aB = stg + aRow128;
        const uint32_t bB = stg + 16384u + bRow128;

        #pragma unroll
        for (int kc = 0; kc < 4; kc++){
            const uint32_t gx = (uint32_t)(2*kc);
            const uint32_t ax = ((gx + aGadd) ^ lrow) << 4;
            const uint32_t bx = ((gx + bGadd) ^ lrow) << 4;
            #pragma unroll
            for (int mt = 0; mt < 4; mt++)
                LDSM4(fa[mt][0], fa[mt][1], fa[mt][2], fa[mt][3],
                      aB + (uint32_t)mt*2048 + ax);
            #pragma unroll
            for (int np = 0; np < 2; np++)
                LDSM4(fb[np][0], fb[np][1], fb[np][2], fb[np][3],
                      bB + (uint32_t)np*2048 + bx);
            #pragma unroll
            for (int mt = 0; mt < 4; mt++)
                #pragma unroll
                for (int nt = 0; nt < 4; nt++)
                    MMA16(c[mt][nt], fa[mt],
                          fb[nt >> 1][(nt & 1) * 2],
                          fb[nt >> 1][(nt & 1) * 2 + 1]);
        }
    }

    // epilogue: fused gather (atomicAdd into out[token])
    const int r0 = lane >> 2;
    const int c0 = (lane & 3) * 2;
    const uint32_t rowbase = (uint32_t)bM * 128 + wm * 64 + r0;
    const size_t   colbase = (size_t)bN * 256 + wn * 32 + c0;
    #pragma unroll
    for (int mt = 0; mt < 4; mt++){
        uint32_t r_lo = rowbase + mt * 16;
        int t_lo = inv[r_lo]     >> 1;
        int t_hi = inv[r_lo + 8] >> 1;
        float* o_lo = C + (size_t)t_lo * HID + colbase;
        float* o_hi = C + (size_t)t_hi * HID + colbase;
        #pragma unroll
        for (int nt = 0; nt < 4; nt++){
            int col = nt * 8;
            atomicAdd(o_lo + col,     c[mt][nt][0]);
            atomicAdd(o_lo + col + 1, c[mt][nt][1]);
            atomicAdd(o_hi + col,     c[mt][nt][2]);
            atomicAdd(o_hi + col + 1, c[mt][nt][3]);
        }
    }
}

// ---------------------------------------------------------------------------
extern "C" void kernel_launch(void* const* d_in, const int* in_sizes, int n_in,
                              void* d_out, int out_size){
    const float* x  = (const float*)d_in[0];   // [8192, 1024]
    const float* w0 = (const float*)d_in[1];   // [8, 1024, 4096]
    const float* w1 = (const float*)d_in[2];   // [8, 4096, 1024]
    const int*   si = (const int*)d_in[3];     // [8192, 2]
    float* out = (float*)d_out;

    void *p_disp, *p_mid, *p_w0t, *p_w1t, *p_inv;
    cudaGetSymbolAddress(&p_disp, g_disp);
    cudaGetSymbolAddress(&p_mid,  g_mid);
    cudaGetSymbolAddress(&p_w0t,  g_w0t);
    cudaGetSymbolAddress(&p_w1t,  g_w1t);
    cudaGetSymbolAddress(&p_inv,  g_inv);

    cudaFuncSetAttribute((const void*)gemm_big<HID, FFN>,
                         cudaFuncAttributeMaxDynamicSharedMemorySize, GEMM_SMEM);
    cudaFuncSetAttribute((const void*)gemm_thin<FFN, FFN/2, HID>,
                         cudaFuncAttributeMaxDynamicSharedMemorySize, GEMM_SMEM);

    // Harness injects 2 launches; 3 preps put gemm0 at ncu skip-index 5.
    transpose_half<<<dim3(FFN/32, HID/32, NEXP), dim3(32,8)>>>(w0, (__half*)p_w0t, HID, FFN);
    transpose_half<<<dim3(HID/32, FFN/32, NEXP), dim3(32,8)>>>(w1, (__half*)p_w1t, FFN, HID);
    scatter_kernel<<<MTOT, 256>>>(x, si, out);

    gemm_big<HID, FFN><<<dim3(FFN/256, MTOT/128), 256, GEMM_SMEM>>>
        ((const __half*)p_disp, (const __half*)p_w0t, (__half*)p_mid);

    gemm_thin<FFN, FFN/2, HID><<<dim3(HID/256, MTOT/128, 2), 512, GEMM_SMEM>>>
        ((const __half*)p_mid, (const __half*)p_w1t, out, (const int*)p_inv);
}

// round 16
// speedup vs baseline: 1.6261x; 1.0943x over previous
#include <cuda_runtime.h>
#include <cuda_fp16.h>
#include <cstdint>

#define NTOKENS 8192
#define TOPK    2
#define HID     1024
#define FFN     4096
#define NEXP    8
#define MTOT    (NTOKENS*TOPK)   // 16384 dispatched rows
#define CAP     (MTOT/NEXP)      // 2048 rows per expert

// Scratch (no cudaMalloc allowed) — fp16 (same 10-bit mantissa as tf32)
__device__ __half g_disp[(size_t)MTOT*HID];       //  32MB fp16 activations
__device__ __half g_mid [(size_t)MTOT*FFN];       // 128MB fp16 GELU output
__device__ __half g_w0t [(size_t)NEXP*HID*FFN];   //  64MB w0^T : [E][FFN][HID] K-major
__device__ __half g_w1t [(size_t)NEXP*FFN*HID];   //  64MB w1^T : [E][HID][FFN] K-major
__device__ int    g_inv [MTOT];                   // dispatched row -> pair index

__device__ __forceinline__ float gelu_f(float v){
    return 0.5f * v * (1.0f + erff(v * 0.70710678118654752440f));
}
__device__ __forceinline__ uint32_t smem_u32(const void* p){
    uint32_t a;
    asm("{ .reg .u64 t; cvta.to.shared.u64 t, %1; cvt.u32.u64 %0, t; }" : "=r"(a) : "l"(p));
    return a;
}

#define CP_ASYNC16(dst, src) \
    asm volatile("cp.async.cg.shared.global [%0], [%1], 16;" :: "r"(dst), "l"(src) : "memory")
#define CP_COMMIT() asm volatile("cp.async.commit_group;" ::: "memory")
#define CP_WAIT(n)  asm volatile("cp.async.wait_group %0;" :: "n"(n) : "memory")

#define LDSM4(r0,r1,r2,r3,a) \
    asm volatile("ldmatrix.sync.aligned.m8n8.x4.shared.b16 {%0,%1,%2,%3}, [%4];" \
        : "=r"(r0),"=r"(r1),"=r"(r2),"=r"(r3) : "r"(a))

#define MMA16(d, a, b0, b1) asm volatile( \
    "mma.sync.aligned.m16n8k16.row.col.f32.f16.f16.f32 " \
    "{%0,%1,%2,%3}, {%4,%5,%6,%7}, {%8,%9}, {%0,%1,%2,%3};\n" \
    : "+f"(d[0]), "+f"(d[1]), "+f"(d[2]), "+f"(d[3]) \
    : "r"(a[0]), "r"(a[1]), "r"(a[2]), "r"(a[3]), "r"(b0), "r"(b1))

// ---------------------------------------------------------------------------
// Prep: transpose [E][R][C] f32 -> [E][C][R] fp16 (rn)
// ---------------------------------------------------------------------------
__global__ void transpose_half(const float* __restrict__ w, __half* __restrict__ wt,
                               int R, int C){
    __shared__ float t[32][33];
    int e = blockIdx.z;
    const float* we = w  + (size_t)e * R * C;
    __half*     wte = wt + (size_t)e * R * C;
    int r0 = blockIdx.y * 32, c0 = blockIdx.x * 32;
    int tx = threadIdx.x, ty = threadIdx.y;
    #pragma unroll
    for (int i = 0; i < 4; i++)
        t[ty + i*8][tx] = we[(size_t)(r0 + ty + i*8) * C + (c0 + tx)];
    __syncthreads();
    #pragma unroll
    for (int i = 0; i < 4; i++)
        wte[(size_t)(c0 + ty + i*8) * R + (r0 + tx)] = __float2half_rn(t[tx][ty + i*8]);
}

// ---------------------------------------------------------------------------
// Scatter (f32 -> fp16) + inverse-index build + out zero-init
// ---------------------------------------------------------------------------
__global__ void scatter_kernel(const float* __restrict__ x, const int* __restrict__ si,
                               float* __restrict__ out){
    int pair = blockIdx.x;
    int t = pair >> 1;
    int dest = si[pair];
    if (threadIdx.x == 0) g_inv[dest] = pair;
    float4 v = ((const float4*)(x + (size_t)t * HID))[threadIdx.x];
    __half2 h01 = __floats2half2_rn(v.x, v.y);
    __half2 h23 = __floats2half2_rn(v.z, v.w);
    uint2 packed = make_uint2(*(uint32_t*)&h01, *(uint32_t*)&h23);
    ((uint2*)(g_disp + (size_t)dest * HID))[threadIdx.x] = packed;
    if ((pair & 1) == 0)
        ((float4*)(out + (size_t)t * HID))[threadIdx.x] = make_float4(0.f,0.f,0.f,0.f);
}

// ---------------------------------------------------------------------------
// fp16 GEMM (f32 accum): CTA tile 128(M) x 128(N), BK=64 (128B rows),
// 3-stage cp.async (32KB/stage = 96KB -> 2 CTAs/SM), 256 threads = 8 warps
// (2m x 4n), warp tile 64x32 (proven ~123-reg layout), launch_bounds(256,2).
// 2 resident CTAs/SM cover each other's barriers / pipeline turns / epilogue.
// EPI 0: mid = fp16(gelu(acc));  EPI 1: atomicAdd(out[token], acc), split-K.
// ---------------------------------------------------------------------------
#define NSTG 3
#define STG_BYTES 32768          // A 16KB + B 16KB (fp16)
#define GEMM_SMEM (NSTG*STG_BYTES)

template<int KSTRIDE, int KRUN, int NTOT, int EPI>
__global__ void __launch_bounds__(256, 2)
gemm_tc(const __half* __restrict__ A, const __half* __restrict__ Bt,
        void* __restrict__ Cv, const int* __restrict__ inv){
    extern __shared__ __align__(1024) char dsm[];
    const uint32_t dynb = smem_u32(dsm);

    const int tid  = threadIdx.x;
    const int lane = tid & 31;
    const int warp = tid >> 5;
    const int wm   = warp & 1;    // 2 m-groups of 64
    const int wn   = warp >> 1;   // 4 n-groups of 32
    const int bN = blockIdx.x, bM = blockIdx.y, kz = blockIdx.z;
    const int e  = bM >> 4;       // 16 row-blocks of 128 per expert
    const int NK = KRUN / 64;

    const __half* Abase = A  + (size_t)bM * 128 * KSTRIDE + (size_t)kz * KRUN;
    const __half* Bbase = Bt + (size_t)e * NTOT * KSTRIDE + (size_t)bN * 128 * KSTRIDE
                             + (size_t)kz * KRUN;

    // ---- producer addressing: 256 threads, 16B granules, 128B rows = 64 k ----
    const uint32_t pr = tid >> 3;          // 0..31
    const uint32_t pg = tid & 7;
    const uint32_t sw = (pg ^ (pr & 7)) * 16;
    const uint32_t aoff0 = pr * 128 + sw;
    const __half* gA0 = Abase + (size_t)pr * KSTRIDE + pg * 8;
    const __half* gB0 = Bbase + (size_t)pr * KSTRIDE + pg * 8;

    // Stage layout: A @0 (16KB: 128 rows), B @16384 (16KB: 128 rows)
    #define ISSUE(t) do {                                                       \
        uint32_t _st = dynb + (uint32_t)((t) % NSTG) * STG_BYTES;               \
        const __half* _ga = gA0 + (size_t)(t) * 64;                             \
        const __half* _gb = gB0 + (size_t)(t) * 64;                             \
        _Pragma("unroll")                                                       \
        for (int _i = 0; _i < 4; _i++)                                          \
            CP_ASYNC16(_st + aoff0 + _i * 4096u, _ga + (size_t)_i * 32 * KSTRIDE); \
        _Pragma("unroll")                                                       \
        for (int _i = 0; _i < 4; _i++)                                          \
            CP_ASYNC16(_st + 16384u + aoff0 + _i * 4096u, _gb + (size_t)_i * 32 * KSTRIDE); \
        } while(0)

    // ---- consumer (ldmatrix) per-lane addressing ----
    const uint32_t mtx  = lane >> 3;
    const uint32_t lrow = lane & 7;
    const uint32_t aRow128 = ((uint32_t)wm*64 + (mtx & 1)*8 + lrow) * 128;
    const uint32_t aGadd   = mtx >> 1;     // k8-half select for A
    const uint32_t bRow128 = ((uint32_t)wn*32 + (mtx >> 1)*8 + lrow) * 128;
    const uint32_t bGadd   = mtx & 1;      // k8-half select for B

    float c[4][4][4];
    #pragma unroll
    for (int i = 0; i < 4; i++)
        #pragma unroll
        for (int j = 0; j < 4; j++){
            c[i][j][0]=0.f; c[i][j][1]=0.f; c[i][j][2]=0.f; c[i][j][3]=0.f;
        }

    // prologue: fill NSTG-1 stages
    #pragma unroll
    for (int p = 0; p < NSTG-1; p++){
        if (p < NK) ISSUE(p);
        CP_COMMIT();
    }

    unsigned fa[4][4];   // [m-tile][reg]   (m16k16 each)
    unsigned fb[2][4];   // [n16-pair][reg] (n16k16 each)

    for (int kt = 0; kt < NK; kt++){
        CP_WAIT(NSTG-2);
        __syncthreads();
        {
            int nt2 = kt + NSTG - 1;
            if (nt2 < NK) ISSUE(nt2);
            CP_COMMIT();
        }
        const uint32_t stg = dynb + (uint32_t)(kt % NSTG) * STG_BYTES;
        const uint32_t aB = stg + aRow128;
        const uint32_t bB = stg + 16384u + bRow128;

        #pragma unroll
        for (int kc = 0; kc < 4; kc++){
            const uint32_t gx = (uint32_t)(2*kc);
            const uint32_t ax = ((gx + aGadd) ^ lrow) << 4;
            const uint32_t bx = ((gx + bGadd) ^ lrow) << 4;
            #pragma unroll
            for (int mt = 0; mt < 4; mt++)
                LDSM4(fa[mt][0], fa[mt][1], fa[mt][2], fa[mt][3],
                      aB + (uint32_t)mt*2048 + ax);
            #pragma unroll
            for (int np = 0; np < 2; np++)
                LDSM4(fb[np][0], fb[np][1], fb[np][2], fb[np][3],
                      bB + (uint32_t)np*2048 + bx);
            #pragma unroll
            for (int mt = 0; mt < 4; mt++)
                #pragma unroll
                for (int nt = 0; nt < 4; nt++)
                    MMA16(c[mt][nt], fa[mt],
                          fb[nt >> 1][(nt & 1) * 2],
                          fb[nt >> 1][(nt & 1) * 2 + 1]);
        }
    }

    // ---- epilogue ----
    const int r0 = lane >> 2;
    const int c0 = (lane & 3) * 2;
    const uint32_t rowbase = (uint32_t)bM * 128 + wm * 64 + r0;
    const size_t   colbase = (size_t)bN * 128 + wn * 32 + c0;
    #pragma unroll
    for (int mt = 0; mt < 4; mt++){
        uint32_t r_lo = rowbase + mt * 16;
        if (EPI == 0){
            __half* C = (__half*)Cv;
            #pragma unroll
            for (int nt = 0; nt < 4; nt++){
                size_t col = colbase + nt * 8;
                __half2 v0 = __floats2half2_rn(gelu_f(c[mt][nt][0]), gelu_f(c[mt][nt][1]));
                __half2 v1 = __floats2half2_rn(gelu_f(c[mt][nt][2]), gelu_f(c[mt][nt][3]));
                *(__half2*)&C[(size_t)r_lo * NTOT + col]       = v0;
                *(__half2*)&C[(size_t)(r_lo + 8) * NTOT + col] = v1;
            }
        } else {
            float* C = (float*)Cv;
            int t_lo = inv[r_lo]     >> 1;
            int t_hi = inv[r_lo + 8] >> 1;
            float* o_lo = C + (size_t)t_lo * HID + colbase;
            float* o_hi = C + (size_t)t_hi * HID + colbase;
            #pragma unroll
            for (int nt = 0; nt < 4; nt++){
                int col = nt * 8;
                atomicAdd(o_lo + col,     c[mt][nt][0]);
                atomicAdd(o_lo + col + 1, c[mt][nt][1]);
                atomicAdd(o_hi + col,     c[mt][nt][2]);
                atomicAdd(o_hi + col + 1, c[mt][nt][3]);
            }
        }
    }
}

// ---------------------------------------------------------------------------
extern "C" void kernel_launch(void* const* d_in, const int* in_sizes, int n_in,
                              void* d_out, int out_size){
    const float* x  = (const float*)d_in[0];   // [8192, 1024]
    const float* w0 = (const float*)d_in[1];   // [8, 1024, 4096]
    const float* w1 = (const float*)d_in[2];   // [8, 4096, 1024]
    const int*   si = (const int*)d_in[3];     // [8192, 2]
    float* out = (float*)d_out;

    void *p_disp, *p_mid, *p_w0t, *p_w1t, *p_inv;
    cudaGetSymbolAddress(&p_disp, g_disp);
    cudaGetSymbolAddress(&p_mid,  g_mid);
    cudaGetSymbolAddress(&p_w0t,  g_w0t);
    cudaGetSymbolAddress(&p_w1t,  g_w1t);
    cudaGetSymbolAddress(&p_inv,  g_inv);

    cudaFuncSetAttribute((const void*)gemm_tc<HID, HID, FFN, 0>,
                         cudaFuncAttributeMaxDynamicSharedMemorySize, GEMM_SMEM);
    cudaFuncSetAttribute((const void*)gemm_tc<FFN, FFN/2, HID, 1>,
                         cudaFuncAttributeMaxDynamicSharedMemorySize, GEMM_SMEM);

    // Harness injects 2 launches; 3 preps put gemm0 at ncu skip-index 5.
    transpose_half<<<dim3(FFN/32, HID/32, NEXP), dim3(32,8)>>>(w0, (__half*)p_w0t, HID, FFN);
    transpose_half<<<dim3(HID/32, FFN/32, NEXP), dim3(32,8)>>>(w1, (__half*)p_w1t, FFN, HID);
    scatter_kernel<<<MTOT, 256>>>(x, si, out);

    gemm_tc<HID, HID, FFN, 0><<<dim3(FFN/128, MTOT/128), 256, GEMM_SMEM>>>
        ((const __half*)p_disp, (const __half*)p_w0t, p_mid, nullptr);

    // split-K=2 (blockIdx.z), fused gather epilogue
    gemm_tc<FFN, FFN/2, HID, 1><<<dim3(HID/128, MTOT/128, 2), 256, GEMM_SMEM>>>
        ((const __half*)p_mid, (const __half*)p_w1t, out, (const int*)p_inv);
}